// round 16
// baseline (speedup 1.0000x reference)
#include <cuda_runtime.h>
#include <cuda_fp16.h>
#include <cstdint>

// Problem constants
#define T_DIM 2048
#define B_DIM 4
#define C_DIM 1024
#define H_DIM 16
#define K_TAPS 15
#define M_DIM (T_DIM * B_DIM)     // 8192 rows (t*B + b)
#define N_DIM (H_DIM * K_TAPS)    // 240 logits per row
#define NPAD  256                 // padded: 16 taps per head
#define KD    C_DIM               // 1024 reduction dim

// Scratch: softmaxed dynamic weights (T*B, 256 padded) fp32
__device__ float g_w[M_DIM * NPAD];

__device__ __forceinline__ uint32_t s2u(const void* p) {
    return (uint32_t)__cvta_generic_to_shared(p);
}

// ========== GEMM: barrier-free mainloop, fp16 mma + fused softmax =========
// R9 structure, but B streams as RAW FP32 from Wlin (no cvt prologue
// kernel): each of 8 warps owns 32 N-cols with a private 2-stage cp.async
// fp32 ring; B mma fragments are built via LDS.64 + cvt.rn.f16x2
// (frag mapping validated in R10). A (64x1024 fp16) resident in smem.
// No bar.sync in the mainloop.
#define NTHR   256
#define BM     64
#define BK     32
#define NTILE  (KD / BK)          // 32 k-tiles
#define ASTH   1032               // A row stride in halves (pad: conflict-free)
#define A_SMEM_H (BM * ASTH)      // 66048 halves = 132096 B
#define BSTF   36                 // B col stride in floats (144B, padded)
#define BW_STG_F (32 * BSTF)      // per-warp stage: 1152 floats = 4608 B
#define B_SMEM_B (8 * 2 * BW_STG_F * 4)        // 73728 B
#define GEMM_SMEM (A_SMEM_H * 2 + B_SMEM_B)    // 205824 B
#define CST    242

extern "C" __global__ void __launch_bounds__(NTHR, 1)
gemm_softmax_kernel(const float* __restrict__ x, const float* __restrict__ W) {
    extern __shared__ __half sh[];
    const int tid  = threadIdx.x;
    const int wid  = tid >> 5;
    const int lane = tid & 31;
    const int m0   = blockIdx.x * BM;
    const int lg   = lane >> 2;
    const int lk   = lane & 3;

    __half* As  = sh;
    float*  Bwf = (float*)(sh + A_SMEM_H) + wid * 2 * BW_STG_F; // warp's ring

    // Warp-private B tile issue (fp32): 32 cols x 32 k = 256 16B-chunks, 8/lane
    auto issue_b = [&](int kb, int st) {
        float* Bs = Bwf + st * BW_STG_F;
        #pragma unroll
        for (int i = 0; i < 8; i++) {
            int idx = i * 32 + lane;
            int nl = idx >> 3, kq = idx & 7;   // col 0..31, chunk 0..7
            int n = wid * 32 + nl;
            int nn = (n < N_DIM) ? n : 0;
            unsigned bytes = (n < N_DIM) ? 16u : 0u;
            const float* src = W + (size_t)nn * KD + kb + kq * 4;
            uint32_t dst = s2u(Bs + nl * BSTF + kq * 4);
            asm volatile("cp.async.cg.shared.global [%0], [%1], 16, %2;\n"
                         :: "r"(dst), "l"(src), "r"(bytes));
        }
        asm volatile("cp.async.commit_group;\n");
    };

    // Prologue: start B ring (depth 2), then load full A (fp32 -> fp16 STS)
    issue_b(0, 0);
    issue_b(BK, 1);

    // A: 64 rows x 1024 = 16384 float4 chunks, 64 per thread
    #pragma unroll 8
    for (int i = 0; i < 64; i++) {
        int idx = i * NTHR + tid;
        int m = idx >> 8, cq = idx & 255;
        float4 v = *(const float4*)(x + (size_t)(m0 + m) * KD + cq * 4);
        __half2 h0 = __floats2half2_rn(v.x, v.y);
        __half2 h1 = __floats2half2_rn(v.z, v.w);
        uint2 o;
        o.x = *(uint32_t*)&h0;
        o.y = *(uint32_t*)&h1;
        *(uint2*)(As + (size_t)m * ASTH + cq * 4) = o;
    }
    __syncthreads();   // A visible to all warps; only sync before the loop

    float acc[4][4][4];   // [m-tile][n-tile][frag]
    #pragma unroll
    for (int a = 0; a < 4; a++)
        #pragma unroll
        for (int b = 0; b < 4; b++)
            #pragma unroll
            for (int c = 0; c < 4; c++) acc[a][b][c] = 0.f;

    for (int j = 0; j < NTILE; j++) {
        if (j == NTILE - 1) asm volatile("cp.async.wait_group 0;\n");
        else                asm volatile("cp.async.wait_group 1;\n");

        const float* Bs = Bwf + (j & 1) * BW_STG_F;
        const int kbase = j * BK;

        #pragma unroll
        for (int kk = 0; kk < BK; kk += 16) {
            uint32_t a[4][4];
            #pragma unroll
            for (int mt = 0; mt < 4; mt++) {
                uint32_t ad = s2u(As + (size_t)(mt * 16 + (lane & 15)) * ASTH
                                     + kbase + kk + (lane >> 4) * 8);
                asm volatile(
                    "ldmatrix.sync.aligned.m8n8.x4.shared.b16 {%0,%1,%2,%3}, [%4];"
                    : "=r"(a[mt][0]), "=r"(a[mt][1]), "=r"(a[mt][2]), "=r"(a[mt][3])
                    : "r"(ad));
            }
            // B frags: LDS.64 fp32 pair + cvt.rn.f16x2 (mapping per R10):
            //   reg r of n8-tile nt: W[col][k], W[col][k+1]
            //   col = wid*32 + nt*8 + lg,  k = kbase+kk + lk*2 + r*8
            uint32_t bfr[4][2];
            #pragma unroll
            for (int nt = 0; nt < 4; nt++) {
                const float* bp = Bs + (nt * 8 + lg) * BSTF + kk + lk * 2;
                #pragma unroll
                for (int r = 0; r < 2; r++) {
                    float2 v = *(const float2*)(bp + r * 8);
                    __half2 h = __floats2half2_rn(v.x, v.y);
                    bfr[nt][r] = *(uint32_t*)&h;
                }
            }
            #pragma unroll
            for (int nt = 0; nt < 4; nt++)
                #pragma unroll
                for (int mt = 0; mt < 4; mt++) {
                    asm volatile(
                        "mma.sync.aligned.m16n8k16.row.col.f32.f16.f16.f32 "
                        "{%0,%1,%2,%3}, {%4,%5,%6,%7}, {%8,%9}, {%0,%1,%2,%3};\n"
                        : "+f"(acc[mt][nt][0]), "+f"(acc[mt][nt][1]),
                          "+f"(acc[mt][nt][2]), "+f"(acc[mt][nt][3])
                        : "r"(a[mt][0]), "r"(a[mt][1]), "r"(a[mt][2]), "r"(a[mt][3]),
                          "r"(bfr[nt][0]), "r"(bfr[nt][1]));
                }
        }

        // Refill the just-consumed stage with tile j+2 (warp-private; all
        // lanes' LDS of this stage precede these issues in program order)
        if (j + 2 < NTILE) issue_b((j + 2) * BK, j & 1);
    }

    // ---- Epilogue: stage C in smem (full-K per warp, no reduction) ----
    __syncthreads();                 // all warps done with A/B smem
    float* Cs = (float*)sh;          // [64][242]

    #pragma unroll
    for (int mt = 0; mt < 4; mt++)
        #pragma unroll
        for (int nt = 0; nt < 4; nt++) {
            int col = wid * 32 + nt * 8 + 2 * lk;
            if (col < N_DIM) {
                int row = mt * 16 + lg;
                Cs[row * CST + col    ]       = acc[mt][nt][0];
                Cs[row * CST + col + 1]       = acc[mt][nt][1];
                Cs[(row + 8) * CST + col    ] = acc[mt][nt][2];
                Cs[(row + 8) * CST + col + 1] = acc[mt][nt][3];
            }
        }
    __syncthreads();

    // Softmax over K=15 per (row, head); write 16-tap-padded rows (stride 256)
    #pragma unroll
    for (int it = 0; it < 4; it++) {
        int task = it * NTHR + tid;          // 64 rows x 16 heads
        int row = task >> 4, h = task & 15;
        const float* p = Cs + row * CST + h * K_TAPS;
        float mx = p[0];
        #pragma unroll
        for (int k = 1; k < K_TAPS; k++) mx = fmaxf(mx, p[k]);
        float e[16];
        float s = 0.f;
        #pragma unroll
        for (int k = 0; k < K_TAPS; k++) { e[k] = __expf(p[k] - mx); s += e[k]; }
        float r = 1.0f / s;
        #pragma unroll
        for (int k = 0; k < K_TAPS; k++) e[k] *= r;
        e[15] = 0.f;
        float4* o4 = (float4*)(g_w + (size_t)(m0 + row) * NPAD + h * 16);
        #pragma unroll
        for (int q = 0; q < 4; q++)
            o4[q] = make_float4(e[4 * q], e[4 * q + 1], e[4 * q + 2], e[4 * q + 3]);
    }
}

// ---------------- Dynamic depthwise conv (causal, K=15) ----------------
// out[t,b,c] = sum_k w[t,b,h(c),k] * x[t+k-14, b, c]
// Exact R9 conv (the 35.3us build): float4/thread, 16-tap padded weights
// (LDS.128 x4), register rolling window, even/odd dual FMA chains.
#define TT 32   // time steps per block

extern "C" __global__ void __launch_bounds__(256, 2)
dynconv_kernel(const float* __restrict__ x, float* __restrict__ out) {
    __shared__ float ws[TT * NPAD];   // 32 KB

    const int tid = threadIdx.x;
    const int t0  = blockIdx.x * TT;
    const int b   = blockIdx.y;

    const int c4 = tid;           // float4 channel group (c = 4*tid)
    const int h  = tid >> 4;      // head

    const float4* x4 = (const float4*)x;
    float4*       o4 = (float4*)out;

    // Register window loads first: 15 independent LDGs in flight
    float4 win[K_TAPS];
    #pragma unroll
    for (int i = 0; i < K_TAPS; i++) {
        int t = t0 - 14 + i;
        win[i] = (t < 0) ? make_float4(0.f, 0.f, 0.f, 0.f)
                         : x4[(size_t)(t * B_DIM + b) * (C_DIM / 4) + c4];
    }

    // Weight tile: TT*256 floats = 2048 float4, 8 per thread
    const float4* gw4 = (const float4*)g_w;
    const size_t wbase = ((size_t)t0 * B_DIM + b) * (NPAD / 4);
    #pragma unroll
    for (int it = 0; it < 8; it++) {
        int idx = it * 256 + tid;            // 0..2047
        int tt = idx >> 6, q = idx & 63;
        ((float4*)ws)[tt * (NPAD / 4) + q] =
            gw4[wbase + (size_t)tt * B_DIM * (NPAD / 4) + q];
    }
    __syncthreads();

    #pragma unroll
    for (int tt = 0; tt < TT; tt++) {
        float4 nxt;
        if (tt + 1 < TT)
            nxt = x4[(size_t)((t0 + tt + 1) * B_DIM + b) * (C_DIM / 4) + c4];

        // 4x LDS.128 weight fetch (tap 15 is zero-padded, unused)
        const float4* w4 = (const float4*)(ws + tt * NPAD + h * 16);
        float4 wq0 = w4[0], wq1 = w4[1], wq2 = w4[2], wq3 = w4[3];
        float w[15] = { wq0.x, wq0.y, wq0.z, wq0.w,
                        wq1.x, wq1.y, wq1.z, wq1.w,
                        wq2.x, wq2.y, wq2.z, wq2.w,
                        wq3.x, wq3.y, wq3.z };

        // Dual accumulator chains (even/odd taps)
        float4 a0 = make_float4(0.f, 0.f, 0.f, 0.f);
        float4 a1 = make_float4(0.f, 0.f, 0.f, 0.f);
        #pragma unroll
        for (int k = 0; k < K_TAPS; k += 2) {
            const float4 xv = win[(tt + k) % K_TAPS];
            a0.x += w[k] * xv.x; a0.y += w[k] * xv.y;
            a0.z += w[k] * xv.z; a0.w += w[k] * xv.w;
        }
        #pragma unroll
        for (int k = 1; k < K_TAPS; k += 2) {
            const float4 xv = win[(tt + k) % K_TAPS];
            a1.x += w[k] * xv.x; a1.y += w[k] * xv.y;
            a1.z += w[k] * xv.z; a1.w += w[k] * xv.w;
        }
        float4 a = make_float4(a0.x + a1.x, a0.y + a1.y,
                               a0.z + a1.z, a0.w + a1.w);
        o4[(size_t)((t0 + tt) * B_DIM + b) * (C_DIM / 4) + c4] = a;
        if (tt + 1 < TT) win[tt % K_TAPS] = nxt;
    }
}

extern "C" void kernel_launch(void* const* d_in, const int* in_sizes, int n_in,
                              void* d_out, int out_size) {
    const float* x    = (const float*)d_in[0];   // (T, B, C) f32
    const float* Wlin = (const float*)d_in[1];   // (240, 1024) f32
    float* out = (float*)d_out;                  // (T, B, C) f32

    cudaFuncSetAttribute(gemm_softmax_kernel,
                         cudaFuncAttributeMaxDynamicSharedMemorySize,
                         GEMM_SMEM);

    gemm_softmax_kernel<<<M_DIM / BM, NTHR, GEMM_SMEM>>>(x, Wlin);
    dynconv_kernel<<<dim3(T_DIM / TT, B_DIM), 256>>>(x, out);
}

// round 17
// speedup vs baseline: 1.1242x; 1.1242x over previous
#include <cuda_runtime.h>
#include <cuda_fp16.h>
#include <cstdint>

// Problem constants
#define T_DIM 2048
#define B_DIM 4
#define C_DIM 1024
#define H_DIM 16
#define K_TAPS 15
#define M_DIM (T_DIM * B_DIM)     // 8192 rows (t*B + b)
#define N_DIM (H_DIM * K_TAPS)    // 240 logits per row
#define NPAD  256                 // padded: 16 taps per head
#define KD    C_DIM               // 1024 reduction dim

// Scratch: softmaxed dynamic weights (T*B, 256 padded) fp32; fp16 Wlin
__device__ float  g_w[M_DIM * NPAD];
__device__ __half g_wh[N_DIM * KD];

__device__ __forceinline__ uint32_t s2u(const void* p) {
    return (uint32_t)__cvta_generic_to_shared(p);
}

// ---------------- Prologue: Wlin -> fp16, once ----------------
extern "C" __global__ void __launch_bounds__(256)
cvt_b_kernel(const float* __restrict__ W) {
    // Let the dependent gemm launch immediately (its A-phase is independent)
    cudaTriggerProgrammaticLaunchCompletion();
    int i = blockIdx.x * 256 + threadIdx.x;      // 61440 float4 total
    float4 v = ((const float4*)W)[i];
    __half2 h0 = __floats2half2_rn(v.x, v.y);
    __half2 h1 = __floats2half2_rn(v.z, v.w);
    uint2 o;
    o.x = *(uint32_t*)&h0;
    o.y = *(uint32_t*)&h1;
    ((uint2*)g_wh)[i] = o;
}

// ========== GEMM: barrier-free mainloop, fp16 mma + fused softmax =========
// (R9 structure — measured ~15.6us.) A (64x1024 fp16) resident in smem;
// each of 8 warps owns 32 N-cols with a private 3-stage cp.async B ring.
// PDL: A-phase (x only) runs before gridDepSync, overlapping cvt.
#define NTHR   256
#define BM     64
#define BK     32
#define NTILE  (KD / BK)          // 32 k-tiles
#define ASTH   1032               // A row stride in halves (pad: conflict-free)
#define A_SMEM_H (BM * ASTH)      // 66048 halves = 132096 B
#define BSTH   40                 // B row stride in halves (80B)
#define BW_STG_H (32 * BSTH)      // per-warp stage: 1280 halves = 2560 B
#define B_SMEM_H (8 * 3 * BW_STG_H)   // 30720 halves = 61440 B
#define GEMM_SMEM ((A_SMEM_H + B_SMEM_H) * 2)  // 193536 B
#define CST    242

extern "C" __global__ void __launch_bounds__(NTHR, 1)
gemm_softmax_kernel(const float* __restrict__ x) {
    extern __shared__ __half sh[];
    const int tid  = threadIdx.x;
    const int wid  = tid >> 5;
    const int lane = tid & 31;
    const int m0   = blockIdx.x * BM;
    const int lg   = lane >> 2;
    const int lk   = lane & 3;

    __half* As = sh;
    __half* Bw = sh + A_SMEM_H + wid * 3 * BW_STG_H;   // this warp's B ring

    // Warp-private B tile issue: 32 cols x 32 k fp16 = 128 16B-chunks, 4/lane
    auto issue_b = [&](int kb, int st) {
        __half* Bs = Bw + st * BW_STG_H;
        #pragma unroll
        for (int i = 0; i < 4; i++) {
            int idx = i * 32 + lane;
            int nl = idx >> 2, kq = idx & 3;
            int n = wid * 32 + nl;
            int nn = (n < N_DIM) ? n : 0;
            unsigned bytes = (n < N_DIM) ? 16u : 0u;
            const __half* src = g_wh + (size_t)nn * KD + kb + kq * 8;
            uint32_t dst = s2u(Bs + nl * BSTH + kq * 8);
            asm volatile("cp.async.cg.shared.global [%0], [%1], 16, %2;\n"
                         :: "r"(dst), "l"(src), "r"(bytes));
        }
        asm volatile("cp.async.commit_group;\n");
    };

    // --- Pre-sync phase: A load (x only, independent of cvt) ---
    // A: 64 rows x 1024 = 16384 float4 chunks, 64 per thread
    #pragma unroll 8
    for (int i = 0; i < 64; i++) {
        int idx = i * NTHR + tid;
        int m = idx >> 8, cq = idx & 255;
        float4 v = *(const float4*)(x + (size_t)(m0 + m) * KD + cq * 4);
        __half2 h0 = __floats2half2_rn(v.x, v.y);
        __half2 h1 = __floats2half2_rn(v.z, v.w);
        uint2 o;
        o.x = *(uint32_t*)&h0;
        o.y = *(uint32_t*)&h1;
        *(uint2*)(As + (size_t)m * ASTH + cq * 4) = o;
    }

    // --- Wait for cvt grid (g_wh visible), then start B ring ---
    cudaGridDependencySynchronize();
    issue_b(0, 0);
    issue_b(BK, 1);

    __syncthreads();   // A visible to all warps; only sync before the loop

    float acc[4][4][4];   // [m-tile][n-tile][frag]
    #pragma unroll
    for (int a = 0; a < 4; a++)
        #pragma unroll
        for (int b = 0; b < 4; b++)
            #pragma unroll
            for (int c = 0; c < 4; c++) acc[a][b][c] = 0.f;

    for (int j = 0; j < NTILE; j++) {
        if (j == NTILE - 1) asm volatile("cp.async.wait_group 0;\n");
        else                asm volatile("cp.async.wait_group 1;\n");

        // Refill early: stage (j+2)%3 was consumed at iter j-1 (warp-private)
        if (j + 2 < NTILE) issue_b((j + 2) * BK, (j + 2) % 3);

        const __half* Bs = Bw + (j % 3) * BW_STG_H;
        const int kbase = j * BK;

        #pragma unroll
        for (int kk = 0; kk < BK; kk += 16) {
            uint32_t a[4][4];
            #pragma unroll
            for (int mt = 0; mt < 4; mt++) {
                uint32_t ad = s2u(As + (size_t)(mt * 16 + (lane & 15)) * ASTH
                                     + kbase + kk + (lane >> 4) * 8);
                asm volatile(
                    "ldmatrix.sync.aligned.m8n8.x4.shared.b16 {%0,%1,%2,%3}, [%4];"
                    : "=r"(a[mt][0]), "=r"(a[mt][1]), "=r"(a[mt][2]), "=r"(a[mt][3])
                    : "r"(ad));
            }
            uint32_t bfr[4][2];
            #pragma unroll
            for (int nh = 0; nh < 2; nh++) {
                int coll = nh * 16 + (lane & 7) + ((lane >> 4) & 1) * 8;
                uint32_t bd = s2u(Bs + coll * BSTH + kk + ((lane >> 3) & 1) * 8);
                uint32_t r0, r1, r2, r3;
                asm volatile(
                    "ldmatrix.sync.aligned.m8n8.x4.shared.b16 {%0,%1,%2,%3}, [%4];"
                    : "=r"(r0), "=r"(r1), "=r"(r2), "=r"(r3) : "r"(bd));
                bfr[nh * 2][0] = r0;  bfr[nh * 2][1] = r1;
                bfr[nh * 2 + 1][0] = r2; bfr[nh * 2 + 1][1] = r3;
            }
            #pragma unroll
            for (int nt = 0; nt < 4; nt++)
                #pragma unroll
                for (int mt = 0; mt < 4; mt++) {
                    asm volatile(
                        "mma.sync.aligned.m16n8k16.row.col.f32.f16.f16.f32 "
                        "{%0,%1,%2,%3}, {%4,%5,%6,%7}, {%8,%9}, {%0,%1,%2,%3};\n"
                        : "+f"(acc[mt][nt][0]), "+f"(acc[mt][nt][1]),
                          "+f"(acc[mt][nt][2]), "+f"(acc[mt][nt][3])
                        : "r"(a[mt][0]), "r"(a[mt][1]), "r"(a[mt][2]), "r"(a[mt][3]),
                          "r"(bfr[nt][0]), "r"(bfr[nt][1]));
                }
        }
    }

    // Mainloop done — let conv blocks launch (they gridDepSync before g_w)
    cudaTriggerProgrammaticLaunchCompletion();

    // ---- Epilogue: stage C in smem (full-K per warp, no reduction) ----
    __syncthreads();                 // all warps done with A/B smem
    float* Cs = (float*)sh;          // [64][242]

    #pragma unroll
    for (int mt = 0; mt < 4; mt++)
        #pragma unroll
        for (int nt = 0; nt < 4; nt++) {
            int col = wid * 32 + nt * 8 + 2 * lk;
            if (col < N_DIM) {
                int row = mt * 16 + lg;
                Cs[row * CST + col    ]       = acc[mt][nt][0];
                Cs[row * CST + col + 1]       = acc[mt][nt][1];
                Cs[(row + 8) * CST + col    ] = acc[mt][nt][2];
                Cs[(row + 8) * CST + col + 1] = acc[mt][nt][3];
            }
        }
    __syncthreads();

    // Softmax over K=15 per (row, head); write 16-tap-padded rows (stride 256)
    #pragma unroll
    for (int it = 0; it < 4; it++) {
        int task = it * NTHR + tid;          // 64 rows x 16 heads
        int row = task >> 4, h = task & 15;
        const float* p = Cs + row * CST + h * K_TAPS;
        float mx = p[0];
        #pragma unroll
        for (int k = 1; k < K_TAPS; k++) mx = fmaxf(mx, p[k]);
        float e[16];
        float s = 0.f;
        #pragma unroll
        for (int k = 0; k < K_TAPS; k++) { e[k] = __expf(p[k] - mx); s += e[k]; }
        float r = 1.0f / s;
        #pragma unroll
        for (int k = 0; k < K_TAPS; k++) e[k] *= r;
        e[15] = 0.f;
        float4* o4 = (float4*)(g_w + (size_t)(m0 + row) * NPAD + h * 16);
        #pragma unroll
        for (int q = 0; q < 4; q++)
            o4[q] = make_float4(e[4 * q], e[4 * q + 1], e[4 * q + 2], e[4 * q + 3]);
    }
}

// ---------------- Dynamic depthwise conv (causal, K=15) ----------------
// out[t,b,c] = sum_k w[t,b,h(c),k] * x[t+k-14, b, c]
// Exact 35.3us conv; PDL: x-window loads run before gridDepSync,
// overlapping the gemm tail (a conv block co-resides with a gemm block).
#define TT 32   // time steps per block

extern "C" __global__ void __launch_bounds__(256, 2)
dynconv_kernel(const float* __restrict__ x, float* __restrict__ out) {
    __shared__ float ws[TT * NPAD];   // 32 KB

    const int tid = threadIdx.x;
    const int t0  = blockIdx.x * TT;
    const int b   = blockIdx.y;

    const int c4 = tid;           // float4 channel group (c = 4*tid)
    const int h  = tid >> 4;      // head

    const float4* x4 = (const float4*)x;
    float4*       o4 = (float4*)out;

    // --- Pre-sync phase: x register window (independent of gemm) ---
    float4 win[K_TAPS];
    #pragma unroll
    for (int i = 0; i < K_TAPS; i++) {
        int t = t0 - 14 + i;
        win[i] = (t < 0) ? make_float4(0.f, 0.f, 0.f, 0.f)
                         : x4[(size_t)(t * B_DIM + b) * (C_DIM / 4) + c4];
    }

    // --- Wait for gemm grid (g_w visible), then load weights ---
    cudaGridDependencySynchronize();

    // Weight tile: TT*256 floats = 2048 float4, 8 per thread
    const float4* gw4 = (const float4*)g_w;
    const size_t wbase = ((size_t)t0 * B_DIM + b) * (NPAD / 4);
    #pragma unroll
    for (int it = 0; it < 8; it++) {
        int idx = it * 256 + tid;            // 0..2047
        int tt = idx >> 6, q = idx & 63;
        ((float4*)ws)[tt * (NPAD / 4) + q] =
            gw4[wbase + (size_t)tt * B_DIM * (NPAD / 4) + q];
    }
    __syncthreads();

    #pragma unroll
    for (int tt = 0; tt < TT; tt++) {
        float4 nxt;
        if (tt + 1 < TT)
            nxt = x4[(size_t)((t0 + tt + 1) * B_DIM + b) * (C_DIM / 4) + c4];

        // 4x LDS.128 weight fetch (tap 15 is zero-padded, unused)
        const float4* w4 = (const float4*)(ws + tt * NPAD + h * 16);
        float4 wq0 = w4[0], wq1 = w4[1], wq2 = w4[2], wq3 = w4[3];
        float w[15] = { wq0.x, wq0.y, wq0.z, wq0.w,
                        wq1.x, wq1.y, wq1.z, wq1.w,
                        wq2.x, wq2.y, wq2.z, wq2.w,
                        wq3.x, wq3.y, wq3.z };

        // Dual accumulator chains (even/odd taps)
        float4 a0 = make_float4(0.f, 0.f, 0.f, 0.f);
        float4 a1 = make_float4(0.f, 0.f, 0.f, 0.f);
        #pragma unroll
        for (int k = 0; k < K_TAPS; k += 2) {
            const float4 xv = win[(tt + k) % K_TAPS];
            a0.x += w[k] * xv.x; a0.y += w[k] * xv.y;
            a0.z += w[k] * xv.z; a0.w += w[k] * xv.w;
        }
        #pragma unroll
        for (int k = 1; k < K_TAPS; k += 2) {
            const float4 xv = win[(tt + k) % K_TAPS];
            a1.x += w[k] * xv.x; a1.y += w[k] * xv.y;
            a1.z += w[k] * xv.z; a1.w += w[k] * xv.w;
        }
        float4 a = make_float4(a0.x + a1.x, a0.y + a1.y,
                               a0.z + a1.z, a0.w + a1.w);
        o4[(size_t)((t0 + tt) * B_DIM + b) * (C_DIM / 4) + c4] = a;
        if (tt + 1 < TT) win[tt % K_TAPS] = nxt;
    }
}

extern "C" void kernel_launch(void* const* d_in, const int* in_sizes, int n_in,
                              void* d_out, int out_size) {
    const float* x    = (const float*)d_in[0];   // (T, B, C) f32
    const float* Wlin = (const float*)d_in[1];   // (240, 1024) f32
    float* out = (float*)d_out;                  // (T, B, C) f32

    cudaFuncSetAttribute(gemm_softmax_kernel,
                         cudaFuncAttributeMaxDynamicSharedMemorySize,
                         GEMM_SMEM);

    // cvt: plain launch
    cvt_b_kernel<<<240, 256>>>(Wlin);

    // gemm: PDL — may launch while cvt runs; syncs before reading g_wh
    {
        cudaLaunchConfig_t cfg = {};
        cudaLaunchAttribute attr[1];
        attr[0].id = cudaLaunchAttributeProgrammaticStreamSerialization;
        attr[0].val.programmaticStreamSerializationAllowed = 1;
        cfg.gridDim = dim3(M_DIM / BM);
        cfg.blockDim = dim3(NTHR);
        cfg.dynamicSmemBytes = GEMM_SMEM;
        cfg.stream = 0;
        cfg.attrs = attr;
        cfg.numAttrs = 1;
        cudaLaunchKernelEx(&cfg, gemm_softmax_kernel, x);
    }

    // conv: PDL — may launch while gemm runs; syncs before reading g_w
    {
        cudaLaunchConfig_t cfg = {};
        cudaLaunchAttribute attr[1];
        attr[0].id = cudaLaunchAttributeProgrammaticStreamSerialization;
        attr[0].val.programmaticStreamSerializationAllowed = 1;
        cfg.gridDim = dim3(T_DIM / TT, B_DIM);
        cfg.blockDim = dim3(256);
        cfg.dynamicSmemBytes = 0;
        cfg.stream = 0;
        cfg.attrs = attr;
        cfg.numAttrs = 1;
        cudaLaunchKernelEx(&cfg, dynconv_kernel, x, out);
    }
}